// round 4
// baseline (speedup 1.0000x reference)
#include <cuda_runtime.h>
#include <cstdint>

#define BT 131072   // B*T = 256*512
#define TT 512

typedef unsigned long long ull;

// ---------------- scratch (device globals; no runtime allocation) ----------
__device__ float g_bufG[67108864];  // [BT,512]  G1 / G2 / Gd2 (reused)
__device__ float g_h1[16777216];    // [BT,128]
__device__ float g_d1[8388608];     // [BT,64]
__device__ float g_d2[16777216];    // [BT,128]
__device__ float g_z[16384];        // [256,64]
__device__ float g_gd1[65536];      // [256,256]

// ---------------- packed f32x2 helpers --------------------------------------
__device__ __forceinline__ ull dup2(float x) {
    ull r; asm("mov.b64 %0, {%1, %1};" : "=l"(r) : "f"(x)); return r;
}
__device__ __forceinline__ ull pack2(float lo, float hi) {
    ull r; asm("mov.b64 %0, {%1, %2};" : "=l"(r) : "f"(lo), "f"(hi)); return r;
}
__device__ __forceinline__ float2 unpack2(ull v) {
    float2 f; asm("mov.b64 {%0, %1}, %2;" : "=f"(f.x), "=f"(f.y) : "l"(v)); return f;
}
__device__ __forceinline__ void fma2(ull& acc, ull a, ull b) {
    asm("fma.rn.f32x2 %0, %1, %2, %0;" : "+l"(acc) : "l"(a), "l"(b));
}
__device__ __forceinline__ ull add2(ull a, ull b) {
    ull d; asm("add.rn.f32x2 %0, %1, %2;" : "=l"(d) : "l"(a), "l"(b)); return d;
}

// fast sigmoid: 1/(1 + 2^(-x*log2e)) via ex2.approx + rcp.approx (~1e-6 rel)
__device__ __forceinline__ float fsig(float x) {
    float r;
    asm("{\n\t.reg .f32 t;\n\t"
        "mul.f32 t, %1, 0fBFB8AA3B;\n\t"
        "ex2.approx.f32 t, t;\n\t"
        "add.f32 t, t, 0f3F800000;\n\t"
        "rcp.approx.f32 %0, t;\n\t}"
        : "=f"(r) : "f"(x));
    return r;
}

// ---------------- misc helpers ----------------------------------------------
__device__ __forceinline__ void cp_async16(void* smem_dst, const void* gmem_src) {
    uint32_t s = (uint32_t)__cvta_generic_to_shared(smem_dst);
    asm volatile("cp.async.cg.shared.global [%0], [%1], 16;\n" :: "r"(s), "l"(gmem_src));
}
__device__ __forceinline__ void cp_async_commit() { asm volatile("cp.async.commit_group;\n"); }
__device__ __forceinline__ void cp_async_wait6()  { asm volatile("cp.async.wait_group 6;\n"); }
__device__ __forceinline__ void cp_async_wait0()  { asm volatile("cp.async.wait_group 0;\n"); }

__device__ __forceinline__ void cluster_sync_() {
    asm volatile("barrier.cluster.arrive.aligned;\n" ::: "memory");
    asm volatile("barrier.cluster.wait.aligned;\n" ::: "memory");
}
__device__ __forceinline__ void st_remote_f32(float* local_ptr, uint32_t peer, float v) {
    uint32_t la = (uint32_t)__cvta_generic_to_shared(local_ptr);
    uint32_t ra;
    asm("mapa.shared::cluster.u32 %0, %1, %2;\n" : "=r"(ra) : "r"(la), "r"(peer));
    asm volatile("st.shared::cluster.f32 [%0], %1;\n" :: "r"(ra), "f"(v) : "memory");
}
__device__ __forceinline__ void mbar_arrive_remote(uint32_t local_mbar, uint32_t peer) {
    uint32_t ra;
    asm("mapa.shared::cluster.u32 %0, %1, %2;\n" : "=r"(ra) : "r"(local_mbar), "r"(peer));
    asm volatile("mbarrier.arrive.release.cluster.shared::cluster.b64 _, [%0];\n"
                 :: "r"(ra) : "memory");
}
__device__ __forceinline__ void mbar_wait(uint32_t mbar, uint32_t parity) {
    asm volatile(
        "{\n\t.reg .pred P;\n"
        "WAITL_%=:\n\t"
        "mbarrier.try_wait.parity.acquire.cluster.shared::cta.b64 P, [%0], %1, 0x989680;\n\t"
        "@!P bra WAITL_%=;\n"
        "}" :: "r"(mbar), "r"(parity) : "memory");
}

// ---------------- bulk GEMM v3: C[M,N] = A[M,K] @ W[K,N] + bias -------------
// Tile 256 x BN, BK=32, 256 threads, per-thread 16 rows x CN cols, f32x2 acc.
// M%256==0, N%BN==0, K%32==0. Dynamic smem: As 2*32*256 + Bs 2*32*BN floats.
template<int BN>
__global__ void __launch_bounds__(256)
gemm3_kernel(const float* __restrict__ A,
             const float* __restrict__ W,
             const float* __restrict__ bias,
             float* __restrict__ C,
             int M, int N, int K) {
    constexpr int CN = BN / 16;          // cols per thread (8 or 4)
    constexpr int NBF4 = (32 * BN / 4) / 256;  // B float4s per thread (4 or 2)
    extern __shared__ float smem[];
    float (*As)[32][256] = (float (*)[32][256])smem;
    float (*Bs)[32][BN] = (float (*)[32][BN])(smem + 2 * 32 * 256);

    const int tid = threadIdx.x;
    const int m0 = blockIdx.x * 256, n0 = blockIdx.y * BN;
    const int ty = tid >> 4, tx = tid & 15;
    const float* Arow = A + (size_t)(m0 + tid) * K;

    ull acc[8][CN];
#pragma unroll
    for (int i = 0; i < 8; i++)
#pragma unroll
        for (int j = 0; j < CN; j++) acc[i][j] = 0ull;

    const int nk = K / 32;

    // prologue: tile 0
    {
        float4 av[8];
#pragma unroll
        for (int q = 0; q < 8; q++) av[q] = *(const float4*)(Arow + q * 4);
#pragma unroll
        for (int q = 0; q < NBF4; q++) {
            int idx = tid * NBF4 + q;
            int bk = idx / (BN / 4), bn = (idx % (BN / 4)) * 4;
            cp_async16(&Bs[0][bk][bn], W + (size_t)bk * N + n0 + bn);
        }
        cp_async_commit();
#pragma unroll
        for (int q = 0; q < 8; q++) {
            As[0][q * 4 + 0][tid] = av[q].x;
            As[0][q * 4 + 1][tid] = av[q].y;
            As[0][q * 4 + 2][tid] = av[q].z;
            As[0][q * 4 + 3][tid] = av[q].w;
        }
        cp_async_wait0();
        __syncthreads();
    }

    for (int kt = 0; kt < nk; kt++) {
        const int p = kt & 1;
        const bool more = (kt + 1) < nk;
        float4 av[8];
        if (more) {
#pragma unroll
            for (int q = 0; q < 8; q++)
                av[q] = *(const float4*)(Arow + (kt + 1) * 32 + q * 4);
#pragma unroll
            for (int q = 0; q < NBF4; q++) {
                int idx = tid * NBF4 + q;
                int bk = idx / (BN / 4), bn = (idx % (BN / 4)) * 4;
                cp_async16(&Bs[p ^ 1][bk][bn], W + (size_t)((kt + 1) * 32 + bk) * N + n0 + bn);
            }
        }
        cp_async_commit();

#pragma unroll 4
        for (int k = 0; k < 32; k++) {
            ull a[8];
#pragma unroll
            for (int q = 0; q < 4; q++) {
                ulonglong2 v = *(const ulonglong2*)&As[p][k][ty * 16 + q * 4];
                a[q * 2] = v.x; a[q * 2 + 1] = v.y;
            }
            ull bd[CN];
#pragma unroll
            for (int q = 0; q < CN / 4; q++) {
                float4 bv = *(const float4*)&Bs[p][k][tx * CN + q * 4];
                bd[q * 4 + 0] = dup2(bv.x); bd[q * 4 + 1] = dup2(bv.y);
                bd[q * 4 + 2] = dup2(bv.z); bd[q * 4 + 3] = dup2(bv.w);
            }
#pragma unroll
            for (int i = 0; i < 8; i++)
#pragma unroll
                for (int j = 0; j < CN; j++) fma2(acc[i][j], a[i], bd[j]);
        }

        if (more) {
#pragma unroll
            for (int q = 0; q < 8; q++) {
                As[p ^ 1][q * 4 + 0][tid] = av[q].x;
                As[p ^ 1][q * 4 + 1][tid] = av[q].y;
                As[p ^ 1][q * 4 + 2][tid] = av[q].z;
                As[p ^ 1][q * 4 + 3][tid] = av[q].w;
            }
        }
        cp_async_wait0();
        __syncthreads();
    }

    // epilogue: bias + store (rows adjacent in acc lanes)
    float bz[CN];
#pragma unroll
    for (int c = 0; c < CN; c++) bz[c] = bias[n0 + tx * CN + c];
#pragma unroll
    for (int i = 0; i < 8; i++) {
        int row0 = m0 + ty * 16 + 2 * i;
        float lo[CN], hi[CN];
#pragma unroll
        for (int c = 0; c < CN; c++) {
            float2 f = unpack2(acc[i][c]);
            lo[c] = f.x + bz[c];
            hi[c] = f.y + bz[c];
        }
#pragma unroll
        for (int q = 0; q < CN / 4; q++) {
            *(float4*)&C[(size_t)row0 * N + n0 + tx * CN + q * 4] =
                make_float4(lo[q * 4], lo[q * 4 + 1], lo[q * 4 + 2], lo[q * 4 + 3]);
            *(float4*)&C[(size_t)(row0 + 1) * N + n0 + tx * CN + q * 4] =
                make_float4(hi[q * 4], hi[q * 4 + 1], hi[q * 4 + 2], hi[q * 4 + 3]);
        }
    }
}

// ---------------- LSTM recurrence, H=64 (encoder L2 / decoder L1) -----------
// 128 CTAs x 256 threads, 2 batch rows per CTA.
// Thread = (row r, h-index j, k-half). Computes all 4 gate partials for (r,j)
// over its 32-k half (weights as 64 u64 k-pairs in regs), combines halves via
// shfl.bfly 16 (partner in-warp), applies gates locally. ONE barrier per step.
__global__ void __launch_bounds__(256)
lstm64_kernel(const float* __restrict__ gproj, // [BT,256] or [256,256] if constProj
              const float* __restrict__ Wr,    // [64,256]
              float* __restrict__ hseq,        // [BT,64] or null
              float* __restrict__ hlast,       // [256,64] or null
              int constProj) {
    __shared__ __align__(16) float h_s[2][2][64];
    __shared__ __align__(16) float gbuf[8][2][256];   // 16KB

    const int tid = threadIdx.x;
    const int b0 = blockIdx.x * 2;
    const int w = tid >> 5, lane = tid & 31;
    const int r = w >> 2;                    // row 0/1
    const int j = (w & 3) * 16 + (lane & 15);
    const int kh = lane >> 4;                // k half: k in [kh*32, kh*32+32)

    // weights: all 4 gates for column j, 16 k-pairs in this thread's half
    ull w2[64];
#pragma unroll
    for (int g = 0; g < 4; g++)
#pragma unroll
        for (int kp = 0; kp < 16; kp++) {
            int k = kh * 32 + 2 * kp;
            w2[g * 16 + kp] = pack2(Wr[k * 256 + g * 64 + j],
                                    Wr[(k + 1) * 256 + g * 64 + j]);
        }

    if (tid < 128) h_s[0][tid >> 6][tid & 63] = 0.f;

    const int pr = tid >> 6, c4 = (tid & 63) * 4;     // prefetch mapping (tid<128)
    float gc[4] = {0.f, 0.f, 0.f, 0.f};
    if (constProj) {
#pragma unroll
        for (int g = 0; g < 4; g++)
            gc[g] = gproj[(size_t)(b0 + r) * 256 + g * 64 + j];
    } else {
        for (int s = 0; s < 7; s++) {
            if (tid < 128)
                cp_async16(&gbuf[s][pr][c4], gproj + ((size_t)(b0 + pr) * TT + s) * 256 + c4);
            cp_async_commit();
        }
        cp_async_wait6();
    }
    __syncthreads();

    float c = 0.f;
    float hcur = 0.f;
    int p = 0;

    for (int t = 0; t < TT; t++) {
        const int st = t & 7;
        if (!constProj) {
            if (tid < 128 && t + 7 < TT)
                cp_async16(&gbuf[(t + 7) & 7][pr][c4],
                           gproj + ((size_t)(b0 + pr) * TT + t + 7) * 256 + c4);
            cp_async_commit();
        }

        // load this thread's 32-k half of h (broadcast LDS)
        ull hv[16];
        const float* hp = &h_s[p][r][kh * 32];
#pragma unroll
        for (int q = 0; q < 8; q++) {
            ulonglong2 v = *(const ulonglong2*)(hp + q * 4);
            hv[q * 2] = v.x; hv[q * 2 + 1] = v.y;
        }

        // 4 gate partial dots (even/odd kp chains for ILP)
        ull ae[4] = {0ull, 0ull, 0ull, 0ull};
        ull ao[4] = {0ull, 0ull, 0ull, 0ull};
#pragma unroll
        for (int kp = 0; kp < 16; kp += 2) {
#pragma unroll
            for (int g = 0; g < 4; g++) {
                fma2(ae[g], w2[g * 16 + kp], hv[kp]);
                fma2(ao[g], w2[g * 16 + kp + 1], hv[kp + 1]);
            }
        }
        float s[4];
#pragma unroll
        for (int g = 0; g < 4; g++) {
            float2 f = unpack2(add2(ae[g], ao[g]));
            s[g] = f.x + f.y;
            s[g] += __shfl_xor_sync(0xffffffffu, s[g], 16);
        }

        float zi, zf, zg, zo;
        if (constProj) {
            zi = s[0] + gc[0]; zf = s[1] + gc[1]; zg = s[2] + gc[2]; zo = s[3] + gc[3];
        } else {
            zi = s[0] + gbuf[st][r][j];
            zf = s[1] + gbuf[st][r][64 + j];
            zg = s[2] + gbuf[st][r][128 + j];
            zo = s[3] + gbuf[st][r][192 + j];
        }
        c = fsig(zf) * c + fsig(zi) * fmaxf(zg, 0.f);
        hcur = fsig(zo) * fmaxf(c, 0.f);
        if (kh == 0) h_s[p ^ 1][r][j] = hcur;
        else if (hseq) hseq[((size_t)(b0 + r) * TT + t) * 64 + j] = hcur;

        if (!constProj) cp_async_wait6();
        __syncthreads();
        p ^= 1;
    }
    if (hlast && kh == 0)
        hlast[(size_t)(b0 + r) * 64 + j] = hcur;
}

// ---------------- LSTM recurrence, H=128 (encoder L1 / decoder L2) ----------
// 2-CTA cluster, 64 clusters, 4 batch rows per CTA. Each CTA owns 256 of the
// 512 gate columns; weights in registers as k-pairs (64 u64).
__global__ void __launch_bounds__(256) __cluster_dims__(2, 1, 1)
lstm128_kernel(const float* __restrict__ gproj, // [BT,512]
               const float* __restrict__ Wr,    // [128,512]
               float* __restrict__ hseq) {      // [BT,128]
    __shared__ __align__(16) float h_s[2][4][128];    // 4KB
    __shared__ __align__(16) float z_s[4][256];       // 4KB
    __shared__ __align__(16) float gbuf[8][4][256];   // 32KB
    __shared__ __align__(8) ull mbar_s;

    const int tid = threadIdx.x;
    uint32_t q;
    asm("mov.u32 %0, %%cluster_ctarank;" : "=r"(q));
    const uint32_t peer = q ^ 1u;
    const int b0 = (blockIdx.x >> 1) * 4;
    const int gcol = (tid >> 6) * 128 + (int)q * 64 + (tid & 63);

    ull w2[64];
#pragma unroll
    for (int kp = 0; kp < 64; kp++)
        w2[kp] = pack2(Wr[(size_t)(2 * kp) * 512 + gcol],
                       Wr[(size_t)(2 * kp + 1) * 512 + gcol]);

    for (int i = tid; i < 512; i += 256) h_s[0][i >> 7][i & 127] = 0.f;
    const uint32_t mbar = (uint32_t)__cvta_generic_to_shared(&mbar_s);
    if (tid == 0)
        asm volatile("mbarrier.init.shared.b64 [%0], %1;\n" :: "r"(mbar), "r"(8u) : "memory");
    __syncthreads();

    const int pr = tid >> 6, c4 = (tid & 63) * 4;
    const int pcol = (c4 >> 6) * 128 + (int)q * 64 + (c4 & 63);
    for (int s = 0; s < 7; s++) {
        cp_async16(&gbuf[s][pr][c4], gproj + ((size_t)(b0 + pr) * TT + s) * 512 + pcol);
        cp_async_commit();
    }
    cp_async_wait6();
    __syncthreads();
    cluster_sync_();

    const int r2 = tid >> 6, jj = tid & 63;
    const int jg = (int)q * 64 + jj;
    const int lane = tid & 31;
    float c = 0.f;
    int p = 0;
    uint32_t par = 0;

    for (int t = 0; t < TT; t++) {
        const int st = t & 7;
        if (t + 7 < TT)
            cp_async16(&gbuf[(t + 7) & 7][pr][c4],
                       gproj + ((size_t)(b0 + pr) * TT + t + 7) * 512 + pcol);
        cp_async_commit();

        ull a[4], e[4];
#pragma unroll
        for (int r = 0; r < 4; r++) { a[r] = 0ull; e[r] = 0ull; }
        const float* h0p = h_s[p][0];
        const float* h1p = h_s[p][1];
        const float* h2p = h_s[p][2];
        const float* h3p = h_s[p][3];
#pragma unroll
        for (int kp = 0; kp < 64; kp += 2) {
            ulonglong2 u0 = *(const ulonglong2*)(h0p + 2 * kp);
            ulonglong2 u1 = *(const ulonglong2*)(h1p + 2 * kp);
            ulonglong2 u2 = *(const ulonglong2*)(h2p + 2 * kp);
            ulonglong2 u3 = *(const ulonglong2*)(h3p + 2 * kp);
            fma2(a[0], w2[kp], u0.x); fma2(e[0], w2[kp + 1], u0.y);
            fma2(a[1], w2[kp], u1.x); fma2(e[1], w2[kp + 1], u1.y);
            fma2(a[2], w2[kp], u2.x); fma2(e[2], w2[kp + 1], u2.y);
            fma2(a[3], w2[kp], u3.x); fma2(e[3], w2[kp + 1], u3.y);
        }
#pragma unroll
        for (int r = 0; r < 4; r++) {
            float2 f = unpack2(add2(a[r], e[r]));
            z_s[r][tid] = gbuf[st][r][tid] + (f.x + f.y);
        }
        __syncthreads();

        {
            float zi = z_s[r2][jj];
            float zf = z_s[r2][64 + jj];
            float zg = z_s[r2][128 + jj];
            float zo = z_s[r2][192 + jj];
            c = fsig(zf) * c + fsig(zi) * fmaxf(zg, 0.f);
            float h = fsig(zo) * fmaxf(c, 0.f);
            float* own = &h_s[p ^ 1][r2][jg];
            *own = h;
            st_remote_f32(own, peer, h);
            hseq[((size_t)(b0 + r2) * TT + t) * 128 + jg] = h;
            __syncwarp();
            if (lane == 0) mbar_arrive_remote(mbar, peer);
        }
        cp_async_wait6();
        __syncthreads();
        mbar_wait(mbar, par);
        par ^= 1;
        p ^= 1;
    }
}

// ---------------- host orchestration ----------------------------------------
extern "C" void kernel_launch(void* const* d_in, const int* in_sizes, int n_in,
                              void* d_out, int out_size) {
    const float* x    = (const float*)d_in[0];
    const float* Wk1  = (const float*)d_in[1];
    const float* Wr1  = (const float*)d_in[2];
    const float* b1   = (const float*)d_in[3];
    const float* Wk2  = (const float*)d_in[4];
    const float* Wr2  = (const float*)d_in[5];
    const float* b2   = (const float*)d_in[6];
    const float* Wd1k = (const float*)d_in[7];
    const float* Wd1r = (const float*)d_in[8];
    const float* bd1  = (const float*)d_in[9];
    const float* Wd2k = (const float*)d_in[10];
    const float* Wd2r = (const float*)d_in[11];
    const float* bd2  = (const float*)d_in[12];
    const float* Wout = (const float*)d_in[13];
    const float* bout = (const float*)d_in[14];
    float* out = (float*)d_out;

    float *bufG, *h1, *d1, *d2, *z, *gd1;
    cudaGetSymbolAddress((void**)&bufG, g_bufG);
    cudaGetSymbolAddress((void**)&h1,  g_h1);
    cudaGetSymbolAddress((void**)&d1,  g_d1);
    cudaGetSymbolAddress((void**)&d2,  g_d2);
    cudaGetSymbolAddress((void**)&z,   g_z);
    cudaGetSymbolAddress((void**)&gd1, g_gd1);

    const int SMEM_G128 = (2 * 32 * 256 + 2 * 32 * 128) * 4;  // 98304
    const int SMEM_G64  = (2 * 32 * 256 + 2 * 32 * 64) * 4;   // 81920
    cudaFuncSetAttribute(gemm3_kernel<128>, cudaFuncAttributeMaxDynamicSharedMemorySize, SMEM_G128);
    cudaFuncSetAttribute(gemm3_kernel<64>,  cudaFuncAttributeMaxDynamicSharedMemorySize, SMEM_G64);

    dim3 blk(256);

    // 1) G1 = x @ Wk1 + b1                     [BT,512]
    gemm3_kernel<128><<<dim3(512, 4), blk, SMEM_G128>>>(x, Wk1, b1, bufG, BT, 512, 64);
    // 2) encoder L1 recurrence -> h1           [BT,128]
    lstm128_kernel<<<128, blk>>>(bufG, Wr1, h1);
    // 3) G2 = h1 @ Wk2 + b2                    [BT,256]
    gemm3_kernel<128><<<dim3(512, 2), blk, SMEM_G128>>>(h1, Wk2, b2, bufG, BT, 256, 128);
    // 4) encoder L2 recurrence -> z (last h)   [256,64]
    lstm64_kernel<<<128, blk>>>(bufG, Wr2, nullptr, z, 0);
    // 5) Gd1 = z @ Wd1k + bd1 (constant/step)  [256,256]
    gemm3_kernel<128><<<dim3(1, 2), blk, SMEM_G128>>>(z, Wd1k, bd1, gd1, 256, 256, 64);
    // 6) decoder L1 recurrence -> d1           [BT,64]
    lstm64_kernel<<<128, blk>>>(gd1, Wd1r, d1, nullptr, 1);
    // 7) Gd2 = d1 @ Wd2k + bd2                 [BT,512]
    gemm3_kernel<128><<<dim3(512, 4), blk, SMEM_G128>>>(d1, Wd2k, bd2, bufG, BT, 512, 64);
    // 8) decoder L2 recurrence -> d2           [BT,128]
    lstm128_kernel<<<128, blk>>>(bufG, Wd2r, d2);
    // 9) out = d2 @ Wout + bout                [BT,64] == [B,T,F]
    gemm3_kernel<64><<<dim3(512, 1), blk, SMEM_G64>>>(d2, Wout, bout, out, BT, 64, 128);
}